// round 16
// baseline (speedup 1.0000x reference)
#include <cuda_runtime.h>
#include <cuda_fp16.h>
#include <cstdint>

#define B_ 256
#define T_ 512
#define D_ 512
#define H_ 256
#define V_ 512

// ---------------- persistent device scratch --------------------------------
__device__ float    g_embWp[2][V_][1024];             // emb@W + b, gate-permuted cols (fp32)
__device__ uint4    g_Uf16[2 * 8 * 16 * 4 * 2 * 32];  // U fp16 b-frags [d][nc][kc16][wn4][p2][lane]
__device__ uint4    g_HA4[2 * 2 * 16 * 512];          // final h (s=511 only) for output kernel

// ---------------- helpers --------------------------------------------------
__device__ __forceinline__ float tapx(float x) {
    float r; asm("tanh.approx.f32 %0, %1;" : "=f"(r) : "f"(x));
    return r;
}
__device__ __forceinline__ float sigx(float x) { return fmaf(tapx(0.5f * x), 0.5f, 0.5f); }
__device__ __forceinline__ void mma16(float* c, unsigned a0, unsigned a1, unsigned a2,
                                      unsigned a3, unsigned b0, unsigned b1) {
    asm volatile(
        "mma.sync.aligned.m16n8k16.row.col.f32.f16.f16.f32 "
        "{%0,%1,%2,%3}, {%4,%5,%6,%7}, {%8,%9}, {%0,%1,%2,%3};\n"
        : "+f"(c[0]), "+f"(c[1]), "+f"(c[2]), "+f"(c[3])
        : "r"(a0), "r"(a1), "r"(a2), "r"(a3), "r"(b0), "r"(b1));
}
__device__ __forceinline__ uint32_t smem_u32(const void* p) {
    uint32_t a;
    asm("{ .reg .u64 t; cvta.to.shared.u64 t, %1; cvt.u32.u64 %0, t; }" : "=r"(a) : "l"(p));
    return a;
}
__device__ __forceinline__ void mbar_wait_cluster(uint32_t bar, unsigned ph) {
    unsigned done;
    do {
        asm volatile(
            "{ .reg .pred p;\n"
            "  mbarrier.try_wait.parity.acquire.cluster.shared::cta.b64 p, [%1], %2, 0x989680;\n"
            "  selp.b32 %0, 1, 0, p; }"
            : "=r"(done) : "r"(bar), "r"(ph) : "memory");
    } while (!done);
}
__host__ __device__ __forceinline__ int perm_col(int gate, int j) {
    return (j >> 5) * 128 + ((j >> 3) & 3) * 32 + ((j >> 1) & 3) * 8
         + (gate >> 1) * 4 + (j & 1) * 2 + (gate & 1);
}

// ---------------- kernel 1: embW precompute (permuted cols, fp32) ----------
__global__ void precompute_embW(const float* __restrict__ emb,
                                const float* __restrict__ W_f, const float* __restrict__ b_f,
                                const float* __restrict__ W_b, const float* __restrict__ b_b) {
    const int d = blockIdx.z;
    const float* W  = d ? W_b : W_f;
    const float* bv = d ? b_b : b_f;
    const int oc = blockIdx.x * 64 + (threadIdx.x & 63);
    const int v0 = blockIdx.y * 16;
    __shared__ float sE[16 * 512];
    for (int i = threadIdx.x; i < 16 * 512; i += 256) sE[i] = emb[v0 * 512 + i];
    __syncthreads();
    const int vq = threadIdx.x >> 6;
    float acc[4] = {0.f, 0.f, 0.f, 0.f};
    for (int k = 0; k < 512; k++) {
        float wv = W[k * 1024 + oc];
#pragma unroll
        for (int i = 0; i < 4; i++) acc[i] += sE[(vq * 4 + i) * 512 + k] * wv;
    }
    const int gate = oc >> 8, j = oc & 255;
    const int pcol = perm_col(gate, j);
    const float bb = bv[oc];
#pragma unroll
    for (int i = 0; i < 4; i++)
        g_embWp[d][v0 + vq * 4 + i][pcol] = acc[i] + bb;
}

// ---------------- kernel 2: U -> fp16 b-frag layout ------------------------
__global__ void build_Uf16(const float* __restrict__ U_f, const float* __restrict__ U_b) {
    int t = blockIdx.x * blockDim.x + threadIdx.x;
    if (t >= 65536) return;
    const int lane = t & 31;
    const int p    = (t >> 5) & 1;
    const int w    = (t >> 6) & 3;
    const int kc   = (t >> 8) & 15;
    const int nc   = (t >> 12) & 7;
    const int d    = (t >> 15) & 1;
    const float* U = d ? U_b : U_f;
    const int l4 = lane & 3, ld4 = lane >> 2;
    const int o8 = ld4;
    const int gate = (o8 & 1) + 2 * (o8 >> 2);
    const int uSel = (o8 >> 1) & 1;
    unsigned vals[4];
#pragma unroll
    for (int i = 0; i < 4; i++) {
        const int ns = 2 * p + (i >> 1);
        const int k0 = kc * 16 + l4 * 2 + (i & 1) * 8;
        const int j  = nc * 32 + w * 8 + ns * 2 + uSel;
        const int col = gate * 256 + j;
        unsigned h0 = (unsigned)__half_as_ushort(__float2half_rn(U[k0 * 1024 + col]));
        unsigned h1 = (unsigned)__half_as_ushort(__float2half_rn(U[(k0 + 1) * 1024 + col]));
        vals[i] = h0 | (h1 << 16);
    }
    g_Uf16[t] = make_uint4(vals[0], vals[1], vals[2], vals[3]);
}

// ---------------- kernel 3: persistent recurrence, DSMEM exchange ----------
// grid = 128 = 32 clusters of 4; cluster = (d, mg), rank = ncp.
// CTA = 16 rows x 256 gate cols; 8 warps. U in registers. ONE count-32
// mbarrier per parity (all 32 producer warps, local included) — zero
// __syncthreads in the steady loop; single convergence point per step.
__global__ void __launch_bounds__(256, 1) __cluster_dims__(4, 1, 1)
lstm_kernel(const int* __restrict__ token_ids) {
    __shared__ __align__(16) unsigned long long mbar[2];      // [parity]
    __shared__ __align__(16) unsigned sBuf[2 * 16 * 128];     // 16KB: [par][kc][reg][ld4][ns]

    const int tid = threadIdx.x;
    const int bx  = blockIdx.x;
    const int d   = bx >> 6;
    const int mg  = (bx >> 2) & 15;
    const int ncp = bx & 3;            // cluster rank
    const int wid = tid >> 5;
    const int w_nl = wid & 3;
    const int l   = tid & 31;
    const int l4  = l & 3, ld4 = l >> 2;
    const bool hi4 = (l4 >= 2);

    const int rk0 = (ncp + 1) & 3, rk1 = (ncp + 2) & 3, rk2 = (ncp + 3) & 3;

    // chunk slot order: 0..3 self, 4..7 rk0, 8..11 rk1, 12..15 rk2
    int kcg[16];
#pragma unroll
    for (int q = 0; q < 4; q++) {
        kcg[q]      = ncp * 4 + q;
        kcg[4 + q]  = rk0 * 4 + q;
        kcg[8 + q]  = rk1 * 4 + q;
        kcg[12 + q] = rk2 * 4 + q;
    }

    // ---- U slice in registers, slot order (constant all steps)
    const int nc = ncp * 2 + (wid >> 2);
    uint4 Breg[16][2];
    {
        const uint4* ub = &g_Uf16[(d * 8 + nc) * 4096];
#pragma unroll
        for (int slot = 0; slot < 16; slot++)
#pragma unroll
            for (int p = 0; p < 2; p++)
                Breg[slot][p] = __ldg(ub + ((kcg[slot] * 4 + w_nl) * 2 + p) * 32 + l);
    }

    const uint32_t barBase = smem_u32(&mbar[0]);
    const uint32_t bufBase = smem_u32(&sBuf[0]);
    if (tid == 0) {
#pragma unroll
        for (int i = 0; i < 2; i++)
            asm volatile("mbarrier.init.shared.b64 [%0], %1;"
                         :: "r"(barBase + i * 8), "r"(32u) : "memory");
    }
    __syncthreads();
    asm volatile("barrier.cluster.arrive.aligned;" ::: "memory");
    asm volatile("barrier.cluster.wait.aligned;" ::: "memory");

    // DSMEM addresses: 3 remote data buffers; all 4 barriers (own included)
    uint32_t rbuf[3], rbarAll[4];
    {
        const int rk[3] = {rk0, rk1, rk2};
#pragma unroll
        for (int i = 0; i < 3; i++) {
            asm("mapa.shared::cluster.u32 %0, %1, %2;" : "=r"(rbuf[i]) : "r"(bufBase), "r"(rk[i]));
            asm("mapa.shared::cluster.u32 %0, %1, %2;" : "=r"(rbarAll[i]) : "r"(barBase), "r"(rk[i]));
        }
        asm("mapa.shared::cluster.u32 %0, %1, %2;" : "=r"(rbarAll[3]) : "r"(barBase), "r"(ncp));
    }

    float cs[4], hs[4];
#pragma unroll
    for (int a = 0; a < 4; a++) { cs[a] = 0.f; hs[a] = 0.f; }

    const int rbase = mg * 16;
    const int kcP = ncp * 4 + (wid >> 1);     // produced k-chunk (global idx)
    const int regP = (hi4 ? 1 : 0) + ((wid & 1) ? 2 : 0);
    const bool prodLane = ((l4 & 1) == 0);

    for (int s = 0; s < T_; s++) {
        const int tt = d ? (T_ - 1 - s) : s;

        const int t0 = token_ids[(rbase + ld4) * T_ + tt];
        const int t1 = token_ids[(rbase + ld4 + 8) * T_ + tt];

        float c_[4][4];
        {
            const float* ea = g_embWp[d][t0] + ncp * 256 + wid * 32;
            const float* eb = g_embWp[d][t1] + ncp * 256 + wid * 32;
#pragma unroll
            for (int ns = 0; ns < 4; ns++) {
                const int cb = ns * 8 + 2 * l4;
                float2 x0 = *(const float2*)(ea + cb);
                float2 x1 = *(const float2*)(eb + cb);
                c_[ns][0] = x0.x; c_[ns][1] = x0.y;
                c_[ns][2] = x1.x; c_[ns][3] = x1.y;
            }
        }

        if (s > 0) {
            const int par = (s - 1) & 1;
            const unsigned ph = (unsigned)(((s - 1) >> 1) & 1);
            const unsigned base = (unsigned)(par * 2048);

            // ---- ONE wait for all 32 producer warps (local + remote)
            mbar_wait_cluster(barBase + par * 8, ph);

            // ---- pipelined feed over all 16 chunks
            unsigned a0, a1, a2, a3, n0, n1, n2, n3;
            a0 = sBuf[base + kcg[0] * 128 + 0 * 32 + l];
            a1 = sBuf[base + kcg[0] * 128 + 1 * 32 + l];
            a2 = sBuf[base + kcg[0] * 128 + 2 * 32 + l];
            a3 = sBuf[base + kcg[0] * 128 + 3 * 32 + l];
#pragma unroll
            for (int slot = 0; slot < 16; slot++) {
                if (slot < 15) {
                    n0 = sBuf[base + kcg[slot + 1] * 128 + 0 * 32 + l];
                    n1 = sBuf[base + kcg[slot + 1] * 128 + 1 * 32 + l];
                    n2 = sBuf[base + kcg[slot + 1] * 128 + 2 * 32 + l];
                    n3 = sBuf[base + kcg[slot + 1] * 128 + 3 * 32 + l];
                }
                mma16(c_[0], a0, a1, a2, a3, Breg[slot][0].x, Breg[slot][0].y);
                mma16(c_[1], a0, a1, a2, a3, Breg[slot][0].z, Breg[slot][0].w);
                mma16(c_[2], a0, a1, a2, a3, Breg[slot][1].x, Breg[slot][1].y);
                mma16(c_[3], a0, a1, a2, a3, Breg[slot][1].z, Breg[slot][1].w);
                a0 = n0; a1 = n1; a2 = n2; a3 = n3;
            }
        }

        // ---- elementwise (register state) + fp16 pack
        const bool msk = (hi4 ? t1 : t0) != 0;
        unsigned words[4];
#pragma unroll
        for (int ns = 0; ns < 4; ns++) {
            float s0 = hi4 ? c_[ns][0] : c_[ns][2];
            float s1 = hi4 ? c_[ns][1] : c_[ns][3];
            float q0 = __shfl_xor_sync(0xffffffffu, s0, 2);
            float q1 = __shfl_xor_sync(0xffffffffu, s1, 2);
            const float zi = hi4 ? q0 : c_[ns][0];
            const float zf = hi4 ? q1 : c_[ns][1];
            const float zg = hi4 ? c_[ns][2] : q0;
            const float zo = hi4 ? c_[ns][3] : q1;
            const float ii = sigx(zi);
            const float ff = sigx(zf);
            const float gg = tapx(zg);
            const float oo = sigx(zo);
            const float cn = fmaf(ff, cs[ns], ii * gg);
            const float hn = oo * tapx(cn);
            const float cn2 = msk ? cn : cs[ns];
            const float hn2 = msk ? hn : hs[ns];
            cs[ns] = cn2;
            hs[ns] = hn2;
            unsigned hb = (unsigned)__half_as_ushort(__float2half_rn(hn2));
            unsigned pb = __shfl_xor_sync(0xffffffffu, hb, 1);
            words[ns] = (hb & 0xffffu) | (pb << 16);
        }

        // ---- publish: local STS + 3 remote DSMEM uint4 stores + 4 arrives
        if (s + 1 < T_) {
            if (prodLane) {
                const unsigned wofs = (unsigned)((s & 1) * 2048 + kcP * 128 + regP * 32 + ld4 * 4);
                uint4 w4 = make_uint4(words[0], words[1], words[2], words[3]);
                *(uint4*)&sBuf[wofs] = w4;
#pragma unroll
                for (int rr = 0; rr < 3; rr++)
                    asm volatile("st.shared::cluster.v4.b32 [%0], {%1,%2,%3,%4};"
                                 :: "r"(rbuf[rr] + wofs * 4),
                                    "r"(w4.x), "r"(w4.y), "r"(w4.z), "r"(w4.w) : "memory");
            }
            __syncwarp();   // orders all lanes' stores before lane 0's release-arrives
            if (l == 0) {
                const unsigned bofs = (unsigned)((s & 1) * 8);
#pragma unroll
                for (int rr = 0; rr < 4; rr++)
                    asm volatile("mbarrier.arrive.release.cluster.shared::cluster.b64 _, [%0];"
                                 :: "r"(rbarAll[rr] + bofs) : "memory");
            }
        } else {
            // final step: publish to global for the output projection
            unsigned* hbase = (unsigned*)(g_HA4 + ((d * 2 + 1) * 16 + mg) * 512);
            if (prodLane) {
#pragma unroll
                for (int ns = 0; ns < 4; ns++)
                    hbase[(kcP * 32 + ld4 * 4 + ns) * 4 + regP] = words[ns];
            }
        }
    }

    asm volatile("barrier.cluster.arrive.aligned;" ::: "memory");
    asm volatile("barrier.cluster.wait.aligned;" ::: "memory");
}

// ---------------- kernel 4: output projection (1 warp / batch row) ---------
__global__ void output_kernel(const float* __restrict__ Wout, const float* __restrict__ bout,
                              float* __restrict__ out) {
    const int b = blockIdx.x;
    const int l = threadIdx.x;
    const int mg = b >> 4, r = b & 15;
    const unsigned* hf = (const unsigned*)(g_HA4 + ((0 * 2 + 1) * 16 + mg) * 512);
    const unsigned* hr = (const unsigned*)(g_HA4 + ((1 * 2 + 1) * 16 + mg) * 512);
    float a0 = 0.f, a1 = 0.f;
#pragma unroll
    for (int i = 0; i < 8; i++) {
        const int k = l * 8 + i;
        const int kc = k >> 4, kj = k & 15;
        const int lc = (r & 7) * 4 + ((kj & 7) >> 1);
        const int reg = ((r >= 8) ? 1 : 0) + ((kj >= 8) ? 2 : 0);
        const int off = (kc * 32 + lc) * 4 + reg;
        unsigned uf = hf[off], ur = hr[off];
        unsigned sf = (kj & 1) ? (uf >> 16) : (uf & 0xffffu);
        unsigned sr = (kj & 1) ? (ur >> 16) : (ur & 0xffffu);
        const float f  = __half2float(__ushort_as_half((unsigned short)sf));
        const float rr = __half2float(__ushort_as_half((unsigned short)sr));
        a0 += f * Wout[2 * k]     + rr * Wout[2 * (H_ + k)];
        a1 += f * Wout[2 * k + 1] + rr * Wout[2 * (H_ + k) + 1];
    }
#pragma unroll
    for (int o = 16; o; o >>= 1) {
        a0 += __shfl_down_sync(0xffffffffu, a0, o);
        a1 += __shfl_down_sync(0xffffffffu, a1, o);
    }
    if (l == 0) {
        out[2 * b]     = a0 + bout[0];
        out[2 * b + 1] = a1 + bout[1];
    }
}

// ---------------- launch ----------------------------------------------------
extern "C" void kernel_launch(void* const* d_in, const int* in_sizes, int n_in,
                              void* d_out, int out_size) {
    const int*   tok   = (const int*)d_in[0];
    const float* emb   = (const float*)d_in[1];
    const float* W_f   = (const float*)d_in[2];
    const float* U_f   = (const float*)d_in[3];
    const float* b_f   = (const float*)d_in[4];
    const float* W_b   = (const float*)d_in[5];
    const float* U_b   = (const float*)d_in[6];
    const float* b_b   = (const float*)d_in[7];
    const float* W_out = (const float*)d_in[8];
    const float* b_out = (const float*)d_in[9];
    float* out = (float*)d_out;

    precompute_embW<<<dim3(16, 32, 2), 256>>>(emb, W_f, b_f, W_b, b_b);
    build_Uf16<<<256, 256>>>(U_f, U_b);
    lstm_kernel<<<128, 256>>>(tok);
    output_kernel<<<B_, 32>>>(W_out, b_out, out);
}

// round 17
// speedup vs baseline: 1.0717x; 1.0717x over previous
#include <cuda_runtime.h>
#include <cuda_fp16.h>
#include <cstdint>

#define B_ 256
#define T_ 512
#define D_ 512
#define H_ 256
#define V_ 512

// ---------------- persistent device scratch --------------------------------
__device__ float    g_embWp[2][V_][1024];             // emb@W + b, gate-permuted cols (fp32)
__device__ uint4    g_Uf16[2 * 8 * 16 * 4 * 2 * 32];  // U fp16 b-frags [d][nc][kc16][wn4][p2][lane]
__device__ uint4    g_HA4[2 * 2 * 16 * 512];          // final h (s=511 only) for output kernel

// ---------------- helpers --------------------------------------------------
__device__ __forceinline__ float tapx(float x) {
    float r; asm("tanh.approx.f32 %0, %1;" : "=f"(r) : "f"(x));
    return r;
}
__device__ __forceinline__ float sigx(float x) { return fmaf(tapx(0.5f * x), 0.5f, 0.5f); }
__device__ __forceinline__ void mma16(float* c, unsigned a0, unsigned a1, unsigned a2,
                                      unsigned a3, unsigned b0, unsigned b1) {
    asm volatile(
        "mma.sync.aligned.m16n8k16.row.col.f32.f16.f16.f32 "
        "{%0,%1,%2,%3}, {%4,%5,%6,%7}, {%8,%9}, {%0,%1,%2,%3};\n"
        : "+f"(c[0]), "+f"(c[1]), "+f"(c[2]), "+f"(c[3])
        : "r"(a0), "r"(a1), "r"(a2), "r"(a3), "r"(b0), "r"(b1));
}
__device__ __forceinline__ uint32_t smem_u32(const void* p) {
    uint32_t a;
    asm("{ .reg .u64 t; cvta.to.shared.u64 t, %1; cvt.u32.u64 %0, t; }" : "=r"(a) : "l"(p));
    return a;
}
__device__ __forceinline__ void mbar_wait_cluster(uint32_t bar, unsigned ph) {
    unsigned done;
    do {
        asm volatile(
            "{ .reg .pred p;\n"
            "  mbarrier.try_wait.parity.acquire.cluster.shared::cta.b64 p, [%1], %2, 0x989680;\n"
            "  selp.b32 %0, 1, 0, p; }"
            : "=r"(done) : "r"(bar), "r"(ph) : "memory");
    } while (!done);
}
__host__ __device__ __forceinline__ int perm_col(int gate, int j) {
    return (j >> 5) * 128 + ((j >> 3) & 3) * 32 + ((j >> 1) & 3) * 8
         + (gate >> 1) * 4 + (j & 1) * 2 + (gate & 1);
}

// ---------------- kernel 1: embW precompute (permuted cols, fp32) ----------
__global__ void precompute_embW(const float* __restrict__ emb,
                                const float* __restrict__ W_f, const float* __restrict__ b_f,
                                const float* __restrict__ W_b, const float* __restrict__ b_b) {
    const int d = blockIdx.z;
    const float* W  = d ? W_b : W_f;
    const float* bv = d ? b_b : b_f;
    const int oc = blockIdx.x * 64 + (threadIdx.x & 63);
    const int v0 = blockIdx.y * 16;
    __shared__ float sE[16 * 512];
    for (int i = threadIdx.x; i < 16 * 512; i += 256) sE[i] = emb[v0 * 512 + i];
    __syncthreads();
    const int vq = threadIdx.x >> 6;
    float acc[4] = {0.f, 0.f, 0.f, 0.f};
    for (int k = 0; k < 512; k++) {
        float wv = W[k * 1024 + oc];
#pragma unroll
        for (int i = 0; i < 4; i++) acc[i] += sE[(vq * 4 + i) * 512 + k] * wv;
    }
    const int gate = oc >> 8, j = oc & 255;
    const int pcol = perm_col(gate, j);
    const float bb = bv[oc];
#pragma unroll
    for (int i = 0; i < 4; i++)
        g_embWp[d][v0 + vq * 4 + i][pcol] = acc[i] + bb;
}

// ---------------- kernel 2: U -> fp16 b-frag layout ------------------------
__global__ void build_Uf16(const float* __restrict__ U_f, const float* __restrict__ U_b) {
    int t = blockIdx.x * blockDim.x + threadIdx.x;
    if (t >= 65536) return;
    const int lane = t & 31;
    const int p    = (t >> 5) & 1;
    const int w    = (t >> 6) & 3;
    const int kc   = (t >> 8) & 15;
    const int nc   = (t >> 12) & 7;
    const int d    = (t >> 15) & 1;
    const float* U = d ? U_b : U_f;
    const int l4 = lane & 3, ld4 = lane >> 2;
    const int o8 = ld4;
    const int gate = (o8 & 1) + 2 * (o8 >> 2);
    const int uSel = (o8 >> 1) & 1;
    unsigned vals[4];
#pragma unroll
    for (int i = 0; i < 4; i++) {
        const int ns = 2 * p + (i >> 1);
        const int k0 = kc * 16 + l4 * 2 + (i & 1) * 8;
        const int j  = nc * 32 + w * 8 + ns * 2 + uSel;
        const int col = gate * 256 + j;
        unsigned h0 = (unsigned)__half_as_ushort(__float2half_rn(U[k0 * 1024 + col]));
        unsigned h1 = (unsigned)__half_as_ushort(__float2half_rn(U[(k0 + 1) * 1024 + col]));
        vals[i] = h0 | (h1 << 16);
    }
    g_Uf16[t] = make_uint4(vals[0], vals[1], vals[2], vals[3]);
}

// ---------------- kernel 3: persistent recurrence, DSMEM exchange ----------
// grid = 128 = 32 clusters of 4; cluster = (d, mg), rank = ncp.
// CTA = 16 rows x 256 gate cols; 8 warps. U in registers. Count-24 mbarrier
// per parity (remote arrivals) + end-of-step __syncthreads (R12 shape).
// NEW: token->embW dependent-load chain software-pipelined one step ahead,
// so every step's mma accumulator init is already in registers.
__global__ void __launch_bounds__(256, 1) __cluster_dims__(4, 1, 1)
lstm_kernel(const int* __restrict__ token_ids) {
    __shared__ __align__(16) unsigned long long mbar[2];      // [parity]
    __shared__ __align__(16) unsigned sBuf[2 * 16 * 128];     // 16KB: [par][kc][reg][ld4][ns]

    const int tid = threadIdx.x;
    const int bx  = blockIdx.x;
    const int d   = bx >> 6;
    const int mg  = (bx >> 2) & 15;
    const int ncp = bx & 3;            // cluster rank
    const int wid = tid >> 5;
    const int w_nl = wid & 3;
    const int l   = tid & 31;
    const int l4  = l & 3, ld4 = l >> 2;
    const bool hi4 = (l4 >= 2);

    // ---- U slice in registers (global chunk order, constant all steps)
    const int nc = ncp * 2 + (wid >> 2);
    uint4 Breg[16][2];
    {
        const uint4* ub = &g_Uf16[(d * 8 + nc) * 4096];
#pragma unroll
        for (int kc = 0; kc < 16; kc++)
#pragma unroll
            for (int p = 0; p < 2; p++)
                Breg[kc][p] = __ldg(ub + ((kc * 4 + w_nl) * 2 + p) * 32 + l);
    }

    const uint32_t barBase = smem_u32(&mbar[0]);
    const uint32_t bufBase = smem_u32(&sBuf[0]);
    if (tid == 0) {
#pragma unroll
        for (int i = 0; i < 2; i++)
            asm volatile("mbarrier.init.shared.b64 [%0], %1;"
                         :: "r"(barBase + i * 8), "r"(24u) : "memory");
    }
    __syncthreads();
    asm volatile("barrier.cluster.arrive.aligned;" ::: "memory");
    asm volatile("barrier.cluster.wait.aligned;" ::: "memory");

    // remote data-buffer and barrier bases for the 3 peer ranks
    uint32_t rbuf[3], rbar[3];
    {
        const int rk[3] = {(ncp + 1) & 3, (ncp + 2) & 3, (ncp + 3) & 3};
#pragma unroll
        for (int i = 0; i < 3; i++) {
            asm("mapa.shared::cluster.u32 %0, %1, %2;" : "=r"(rbuf[i]) : "r"(bufBase), "r"(rk[i]));
            asm("mapa.shared::cluster.u32 %0, %1, %2;" : "=r"(rbar[i]) : "r"(barBase), "r"(rk[i]));
        }
    }

    float cs[4], hs[4];
#pragma unroll
    for (int a = 0; a < 4; a++) { cs[a] = 0.f; hs[a] = 0.f; }

    const int rbase = mg * 16;
    const int kcP = ncp * 4 + (wid >> 1);     // produced k-chunk (global idx)
    const int regP = (hi4 ? 1 : 0) + ((wid & 1) ? 2 : 0);
    const bool prodLane = ((l4 & 1) == 0);
    const float* embBase = &g_embWp[d][0][ncp * 256 + wid * 32];

    // ---- preload step-0 tokens + embW accumulator init
    int tA, tB;
    float cN[4][4];
    {
        const int tt0 = d ? (T_ - 1) : 0;
        tA = token_ids[(rbase + ld4) * T_ + tt0];
        tB = token_ids[(rbase + ld4 + 8) * T_ + tt0];
        const float* ea = embBase + (size_t)tA * 1024;
        const float* eb = embBase + (size_t)tB * 1024;
#pragma unroll
        for (int ns = 0; ns < 4; ns++) {
            const int cb = ns * 8 + 2 * l4;
            float2 x0 = *(const float2*)(ea + cb);
            float2 x1 = *(const float2*)(eb + cb);
            cN[ns][0] = x0.x; cN[ns][1] = x0.y;
            cN[ns][2] = x1.x; cN[ns][3] = x1.y;
        }
    }

    for (int s = 0; s < T_; s++) {
        // current-step tokens + accumulator (already in registers)
        const int t0 = tA, t1 = tB;
        float c_[4][4];
#pragma unroll
        for (int ns = 0; ns < 4; ns++)
#pragma unroll
            for (int i = 0; i < 4; i++) c_[ns][i] = cN[ns][i];

        // ---- prefetch tokens for s+1 (latency hidden by wait + mma feed)
        if (s + 1 < T_) {
            const int tt1 = d ? (T_ - 2 - s) : (s + 1);
            tA = token_ids[(rbase + ld4) * T_ + tt1];
            tB = token_ids[(rbase + ld4 + 8) * T_ + tt1];
        }

        if (s > 0) {
            const int par = (s - 1) & 1;
            const unsigned ph = (unsigned)(((s - 1) >> 1) & 1);
            mbar_wait_cluster(barBase + par * 8, ph);

            const unsigned* src = &sBuf[par * 2048];
            // software-pipelined feed: 4 LDS.32 + 4 mma per chunk, prefetch next
            unsigned a0, a1, a2, a3, n0, n1, n2, n3;
            a0 = src[0 * 128 + 0 * 32 + l];
            a1 = src[0 * 128 + 1 * 32 + l];
            a2 = src[0 * 128 + 2 * 32 + l];
            a3 = src[0 * 128 + 3 * 32 + l];
#pragma unroll
            for (int kc = 0; kc < 16; kc++) {
                if (kc < 15) {
                    n0 = src[(kc + 1) * 128 + 0 * 32 + l];
                    n1 = src[(kc + 1) * 128 + 1 * 32 + l];
                    n2 = src[(kc + 1) * 128 + 2 * 32 + l];
                    n3 = src[(kc + 1) * 128 + 3 * 32 + l];
                }
                mma16(c_[0], a0, a1, a2, a3, Breg[kc][0].x, Breg[kc][0].y);
                mma16(c_[1], a0, a1, a2, a3, Breg[kc][0].z, Breg[kc][0].w);
                mma16(c_[2], a0, a1, a2, a3, Breg[kc][1].x, Breg[kc][1].y);
                mma16(c_[3], a0, a1, a2, a3, Breg[kc][1].z, Breg[kc][1].w);
                a0 = n0; a1 = n1; a2 = n2; a3 = n3;
            }
        }

        // ---- prefetch embW for s+1 into cN (tA/tB arrived during the feed;
        //      results needed only after elementwise+publish+BAR+wait)
        if (s + 1 < T_) {
            const float* ea = embBase + (size_t)tA * 1024;
            const float* eb = embBase + (size_t)tB * 1024;
#pragma unroll
            for (int ns = 0; ns < 4; ns++) {
                const int cb = ns * 8 + 2 * l4;
                float2 x0 = *(const float2*)(ea + cb);
                float2 x1 = *(const float2*)(eb + cb);
                cN[ns][0] = x0.x; cN[ns][1] = x0.y;
                cN[ns][2] = x1.x; cN[ns][3] = x1.y;
            }
        }

        // ---- elementwise (register state) + fp16 pack
        const bool msk = (hi4 ? t1 : t0) != 0;
        unsigned words[4];
#pragma unroll
        for (int ns = 0; ns < 4; ns++) {
            float s0 = hi4 ? c_[ns][0] : c_[ns][2];
            float s1 = hi4 ? c_[ns][1] : c_[ns][3];
            float q0 = __shfl_xor_sync(0xffffffffu, s0, 2);
            float q1 = __shfl_xor_sync(0xffffffffu, s1, 2);
            const float zi = hi4 ? q0 : c_[ns][0];
            const float zf = hi4 ? q1 : c_[ns][1];
            const float zg = hi4 ? c_[ns][2] : q0;
            const float zo = hi4 ? c_[ns][3] : q1;
            const float ii = sigx(zi);
            const float ff = sigx(zf);
            const float gg = tapx(zg);
            const float oo = sigx(zo);
            const float cn = fmaf(ff, cs[ns], ii * gg);
            const float hn = oo * tapx(cn);
            const float cn2 = msk ? cn : cs[ns];
            const float hn2 = msk ? hn : hs[ns];
            cs[ns] = cn2;
            hs[ns] = hn2;
            unsigned hb = (unsigned)__half_as_ushort(__float2half_rn(hn2));
            unsigned pb = __shfl_xor_sync(0xffffffffu, hb, 1);
            words[ns] = (hb & 0xffffu) | (pb << 16);
        }

        // ---- publish: local STS + 3 remote DSMEM uint4 stores
        if (s + 1 < T_) {
            if (prodLane) {
                const unsigned wofs = (unsigned)((s & 1) * 2048 + kcP * 128 + regP * 32 + ld4 * 4);
                uint4 w4 = make_uint4(words[0], words[1], words[2], words[3]);
                *(uint4*)&sBuf[wofs] = w4;
#pragma unroll
                for (int rr = 0; rr < 3; rr++)
                    asm volatile("st.shared::cluster.v4.b32 [%0], {%1,%2,%3,%4};"
                                 :: "r"(rbuf[rr] + wofs * 4),
                                    "r"(w4.x), "r"(w4.y), "r"(w4.z), "r"(w4.w) : "memory");
            }
            __syncwarp();   // orders all lanes' stores before lane 0's release-arrives
            if (l == 0) {
                const unsigned bofs = (unsigned)((s & 1) * 8);
#pragma unroll
                for (int rr = 0; rr < 3; rr++)
                    asm volatile("mbarrier.arrive.release.cluster.shared::cluster.b64 _, [%0];"
                                 :: "r"(rbar[rr] + bofs) : "memory");
            }
        } else {
            // final step: publish to global for the output projection
            unsigned* hbase = (unsigned*)(g_HA4 + ((d * 2 + 1) * 16 + mg) * 512);
            if (prodLane) {
#pragma unroll
                for (int ns = 0; ns < 4; ns++)
                    hbase[(kcP * 32 + ld4 * 4 + ns) * 4 + regP] = words[ns];
            }
        }
        __syncthreads();  // self-chunk visibility + intra-CTA parity reuse
    }

    asm volatile("barrier.cluster.arrive.aligned;" ::: "memory");
    asm volatile("barrier.cluster.wait.aligned;" ::: "memory");
}

// ---------------- kernel 4: output projection (1 warp / batch row) ---------
__global__ void output_kernel(const float* __restrict__ Wout, const float* __restrict__ bout,
                              float* __restrict__ out) {
    const int b = blockIdx.x;
    const int l = threadIdx.x;
    const int mg = b >> 4, r = b & 15;
    const unsigned* hf = (const unsigned*)(g_HA4 + ((0 * 2 + 1) * 16 + mg) * 512);
    const unsigned* hr = (const unsigned*)(g_HA4 + ((1 * 2 + 1) * 16 + mg) * 512);
    float a0 = 0.f, a1 = 0.f;
#pragma unroll
    for (int i = 0; i < 8; i++) {
        const int k = l * 8 + i;
        const int kc = k >> 4, kj = k & 15;
        const int lc = (r & 7) * 4 + ((kj & 7) >> 1);
        const int reg = ((r >= 8) ? 1 : 0) + ((kj >= 8) ? 2 : 0);
        const int off = (kc * 32 + lc) * 4 + reg;
        unsigned uf = hf[off], ur = hr[off];
        unsigned sf = (kj & 1) ? (uf >> 16) : (uf & 0xffffu);
        unsigned sr = (kj & 1) ? (ur >> 16) : (ur & 0xffffu);
        const float f  = __half2float(__ushort_as_half((unsigned short)sf));
        const float rr = __half2float(__ushort_as_half((unsigned short)sr));
        a0 += f * Wout[2 * k]     + rr * Wout[2 * (H_ + k)];
        a1 += f * Wout[2 * k + 1] + rr * Wout[2 * (H_ + k) + 1];
    }
#pragma unroll
    for (int o = 16; o; o >>= 1) {
        a0 += __shfl_down_sync(0xffffffffu, a0, o);
        a1 += __shfl_down_sync(0xffffffffu, a1, o);
    }
    if (l == 0) {
        out[2 * b]     = a0 + bout[0];
        out[2 * b + 1] = a1 + bout[1];
    }
}

// ---------------- launch ----------------------------------------------------
extern "C" void kernel_launch(void* const* d_in, const int* in_sizes, int n_in,
                              void* d_out, int out_size) {
    const int*   tok   = (const int*)d_in[0];
    const float* emb   = (const float*)d_in[1];
    const float* W_f   = (const float*)d_in[2];
    const float* U_f   = (const float*)d_in[3];
    const float* b_f   = (const float*)d_in[4];
    const float* W_b   = (const float*)d_in[5];
    const float* U_b   = (const float*)d_in[6];
    const float* b_b   = (const float*)d_in[7];
    const float* W_out = (const float*)d_in[8];
    const float* b_out = (const float*)d_in[9];
    float* out = (float*)d_out;

    precompute_embW<<<dim3(16, 32, 2), 256>>>(emb, W_f, b_f, W_b, b_b);
    build_Uf16<<<256, 256>>>(U_f, U_b);
    lstm_kernel<<<128, 256>>>(tok);
    output_kernel<<<B_, 32>>>(W_out, b_out, out);
}